// round 9
// baseline (speedup 1.0000x reference)
#include <cuda_runtime.h>
#include <cuda_fp16.h>
#include <stdint.h>

#define D_IN   256
#define D_HID  64
#define D_EMB  32
#define MAX_NODES 100000

// Scratch (static __device__ — no allocation allowed)
__device__ __half g_Hh [MAX_NODES * D_HID];  // x @ W1            (fp16)
__device__ float  g_S1 [MAX_NODES * D_HID];  // A @ H             (fp32)
__device__ __half g_Z1h[MAX_NODES * D_EMB];  // relu(S1+b1) @ W2  (fp16)
__device__ float  g_S2 [MAX_NODES * D_EMB];  // A @ Z1            (fp32)
__device__ __half g_S2h[MAX_NODES * D_EMB];  // fp16 (S2+b2) for decoder

// ---------------------------------------------------------------------------
// TF32 helpers
// ---------------------------------------------------------------------------
__device__ __forceinline__ unsigned f2tf32(float f) {
    unsigned r;
    asm("cvt.rna.tf32.f32 %0, %1;" : "=r"(r) : "f"(f));
    return r;
}
__device__ __forceinline__ unsigned bits2tf32(unsigned b) {
    unsigned r;
    asm("cvt.rna.tf32.f32 %0, %1;" : "=r"(r) : "r"(b));
    return r;
}

__device__ __forceinline__ void mma_tf32(
    float& d0, float& d1, float& d2, float& d3,
    unsigned a0, unsigned a1, unsigned a2, unsigned a3,
    unsigned b0, unsigned b1)
{
    asm volatile(
        "mma.sync.aligned.m16n8k8.row.col.f32.tf32.tf32.f32 "
        "{%0,%1,%2,%3}, {%4,%5,%6,%7}, {%8,%9}, {%0,%1,%2,%3};"
        : "+f"(d0), "+f"(d1), "+f"(d2), "+f"(d3)
        : "r"(a0), "r"(a1), "r"(a2), "r"(a3), "r"(b0), "r"(b1));
}

__device__ __forceinline__ void cp_async16(unsigned smem_addr, const void* gptr) {
    asm volatile("cp.async.cg.shared.global [%0], [%1], 16;"
                 :: "r"(smem_addr), "l"(gptr));
}

// ---------------------------------------------------------------------------
// GEMM1 (TF32 + cp.async double buffer + fused zeroing), fp16 output
// ---------------------------------------------------------------------------
#define W_STRIDE 72
#define X_STRIDE 36
#define W_WORDS  (256 * W_STRIDE)
#define X_WORDS  (128 * X_STRIDE)
#define GEMM1_SMEM ((W_WORDS + 2 * X_WORDS) * 4)

__global__ __launch_bounds__(256) void gemm1_tf32_v4(
    const float* __restrict__ x, const float* __restrict__ W1, int n)
{
    extern __shared__ unsigned smem[];
    unsigned* Wsh = smem;                       // [256][72]
    float*    xsf = (float*)(smem + W_WORDS);   // [2][128][36]

    int tid  = threadIdx.x;
    int warp = tid >> 5;
    int lane = tid & 31;
    int row_base = blockIdx.x * 128;
    int wm   = warp * 16;
    int qrow = lane >> 2;
    int qcol = lane & 3;

    unsigned xs_base;
    asm("{ .reg .u64 t; cvta.to.shared.u64 t, %1; cvt.u32.u64 %0, t; }"
        : "=r"(xs_base) : "l"(xsf));

    #pragma unroll
    for (int l = 0; l < 4; l++) {
        int flat = tid + l * 256;
        int r    = flat >> 3;
        int c4   = flat & 7;
        int grow = row_base + r; if (grow >= n) grow = n - 1;
        cp_async16(xs_base + (unsigned)(r * X_STRIDE + c4 * 4) * 4,
                   x + (size_t)grow * D_IN + c4 * 4);
    }
    asm volatile("cp.async.commit_group;");

    #pragma unroll
    for (int l = 0; l < 16; l++) {
        int flat = tid + l * 256;
        int k  = flat >> 4;
        int cc = (flat & 15) * 4;
        float4 w = __ldg((const float4*)(W1 + (size_t)k * 64 + cc));
        Wsh[k * W_STRIDE + cc + 0] = f2tf32(w.x);
        Wsh[k * W_STRIDE + cc + 1] = f2tf32(w.y);
        Wsh[k * W_STRIDE + cc + 2] = f2tf32(w.z);
        Wsh[k * W_STRIDE + cc + 3] = f2tf32(w.w);
    }

    {
        int gtid = blockIdx.x * 256 + tid;
        int nthr = gridDim.x * 256;
        float4 z = make_float4(0.f, 0.f, 0.f, 0.f);
        for (int i = gtid; i < n * 16; i += nthr) ((float4*)g_S1)[i] = z;
        for (int i = gtid; i < n * 8;  i += nthr) ((float4*)g_S2)[i] = z;
    }

    float c[8][4];
    #pragma unroll
    for (int nt = 0; nt < 8; nt++)
        #pragma unroll
        for (int i = 0; i < 4; i++) c[nt][i] = 0.f;

    #pragma unroll
    for (int kc = 0; kc < 8; kc++) {
        if (kc + 1 < 8) {
            int buf = (kc + 1) & 1;
            #pragma unroll
            for (int l = 0; l < 4; l++) {
                int flat = tid + l * 256;
                int r    = flat >> 3;
                int c4   = flat & 7;
                int grow = row_base + r; if (grow >= n) grow = n - 1;
                cp_async16(xs_base + (unsigned)(buf * X_WORDS + r * X_STRIDE + c4 * 4) * 4,
                           x + (size_t)grow * D_IN + (kc + 1) * 32 + c4 * 4);
            }
            asm volatile("cp.async.commit_group;");
            asm volatile("cp.async.wait_group 1;");
        } else {
            asm volatile("cp.async.wait_group 0;");
        }
        __syncthreads();

        const unsigned* xb = (const unsigned*)(xsf + (kc & 1) * X_WORDS);
        #pragma unroll
        for (int k8 = 0; k8 < 4; k8++) {
            int ar = wm + qrow;
            int ac = k8 * 8 + qcol;
            unsigned a0 = bits2tf32(xb[(ar    ) * X_STRIDE + ac    ]);
            unsigned a1 = bits2tf32(xb[(ar + 8) * X_STRIDE + ac    ]);
            unsigned a2 = bits2tf32(xb[(ar    ) * X_STRIDE + ac + 4]);
            unsigned a3 = bits2tf32(xb[(ar + 8) * X_STRIDE + ac + 4]);
            int kg = kc * 32 + k8 * 8 + qcol;
            #pragma unroll
            for (int nt = 0; nt < 8; nt++) {
                unsigned b0 = Wsh[(kg    ) * W_STRIDE + nt * 8 + qrow];
                unsigned b1 = Wsh[(kg + 4) * W_STRIDE + nt * 8 + qrow];
                mma_tf32(c[nt][0], c[nt][1], c[nt][2], c[nt][3],
                         a0, a1, a2, a3, b0, b1);
            }
        }
        __syncthreads();
    }

    int r0 = row_base + wm + qrow;
    int cb = qcol * 2;
    #pragma unroll
    for (int nt = 0; nt < 8; nt++) {
        if (r0 < n)
            *(__half2*)(g_Hh + (size_t)r0 * D_HID + nt*8 + cb) =
                __floats2half2_rn(c[nt][0], c[nt][1]);
        if (r0 + 8 < n)
            *(__half2*)(g_Hh + (size_t)(r0 + 8) * D_HID + nt*8 + cb) =
                __floats2half2_rn(c[nt][2], c[nt][3]);
    }
}

// ---------------------------------------------------------------------------
// red.v4 helper
// ---------------------------------------------------------------------------
__device__ __forceinline__ void red_add_v4(float* p, float4 v) {
    asm volatile("red.global.add.v4.f32 [%0], {%1,%2,%3,%4};"
                 :: "l"(p), "f"(v.x), "f"(v.y), "f"(v.z), "f"(v.w)
                 : "memory");
}

#define EPB 1024   // edges per block (smem-staged)

// ---------------------------------------------------------------------------
// Edge staging: coalesced int4/float4 loads -> smem (int2 sd + float v)
// ---------------------------------------------------------------------------
__device__ __forceinline__ void stage_edges(
    const int* __restrict__ src, const int* __restrict__ dst,
    const float* __restrict__ val, int nnz,
    int2* sd, float* sv)
{
    long long eb = (long long)blockIdx.x * EPB;
    int tid = threadIdx.x;
    if (eb + EPB <= nnz) {
        int4   s4 = __ldg((const int4*)  (src + eb) + tid);
        int4   d4 = __ldg((const int4*)  (dst + eb) + tid);
        float4 v4 = __ldg((const float4*)(val + eb) + tid);
        sd[tid*4+0] = make_int2(s4.x, d4.x);
        sd[tid*4+1] = make_int2(s4.y, d4.y);
        sd[tid*4+2] = make_int2(s4.z, d4.z);
        sd[tid*4+3] = make_int2(s4.w, d4.w);
        sv[tid*4+0] = v4.x; sv[tid*4+1] = v4.y;
        sv[tid*4+2] = v4.z; sv[tid*4+3] = v4.w;
    } else {
        #pragma unroll
        for (int k = 0; k < 4; k++) {
            long long e = eb + tid * 4 + k;
            bool ok = (e < nnz);
            long long ec = ok ? e : 0;
            sd[tid*4+k] = make_int2(__ldg(src + ec), __ldg(dst + ec));
            sv[tid*4+k] = ok ? __ldg(val + ec) : 0.f;
        }
    }
    __syncthreads();
}

// ---------------------------------------------------------------------------
// SpMM d=64 (fp16 gather, smem-staged indices): 16-lane groups, 64 edges each.
// ---------------------------------------------------------------------------
__global__ __launch_bounds__(256) void spmm64_kernel(
    const int* __restrict__ src, const int* __restrict__ dst,
    const float* __restrict__ val, int nnz)
{
    __shared__ int2  sd[EPB];
    __shared__ float sv[EPB];
    stage_edges(src, dst, val, nnz, sd, sv);

    int tid = threadIdx.x;
    int c = tid & 15;
    int g = tid >> 4;                 // 16 groups
    int eb = g * 64;

    #pragma unroll 4
    for (int j = 0; j < 64; j += 4) {
        int2  e0 = sd[eb+j+0], e1 = sd[eb+j+1], e2 = sd[eb+j+2], e3 = sd[eb+j+3];
        float v0 = sv[eb+j+0], v1 = sv[eb+j+1], v2 = sv[eb+j+2], v3 = sv[eb+j+3];

        uint2 r0 = __ldg((const uint2*)(g_Hh + (size_t)e0.x * D_HID) + c);
        uint2 r1 = __ldg((const uint2*)(g_Hh + (size_t)e1.x * D_HID) + c);
        uint2 r2 = __ldg((const uint2*)(g_Hh + (size_t)e2.x * D_HID) + c);
        uint2 r3 = __ldg((const uint2*)(g_Hh + (size_t)e3.x * D_HID) + c);

        float2 f0a = __half22float2(*(__half2*)&r0.x), f0b = __half22float2(*(__half2*)&r0.y);
        float2 f1a = __half22float2(*(__half2*)&r1.x), f1b = __half22float2(*(__half2*)&r1.y);
        float2 f2a = __half22float2(*(__half2*)&r2.x), f2b = __half22float2(*(__half2*)&r2.y);
        float2 f3a = __half22float2(*(__half2*)&r3.x), f3b = __half22float2(*(__half2*)&r3.y);

        red_add_v4(g_S1 + (size_t)e0.y * D_HID + c*4, make_float4(v0*f0a.x, v0*f0a.y, v0*f0b.x, v0*f0b.y));
        red_add_v4(g_S1 + (size_t)e1.y * D_HID + c*4, make_float4(v1*f1a.x, v1*f1a.y, v1*f1b.x, v1*f1b.y));
        red_add_v4(g_S1 + (size_t)e2.y * D_HID + c*4, make_float4(v2*f2a.x, v2*f2a.y, v2*f2b.x, v2*f2b.y));
        red_add_v4(g_S1 + (size_t)e3.y * D_HID + c*4, make_float4(v3*f3a.x, v3*f3a.y, v3*f3b.x, v3*f3b.y));
    }
}

// ---------------------------------------------------------------------------
// GEMM2: Z1 = relu(S1 + b1) @ W2, fp16 output
// ---------------------------------------------------------------------------
__global__ __launch_bounds__(256) void gemm2_kernel(
    const float* __restrict__ b1, const float* __restrict__ W2, int n)
{
    __shared__ float zs[64][65];
    __shared__ float ws[64][32];

    int tid = threadIdx.x;
    int row_base = blockIdx.x * 64;

    #pragma unroll
    for (int l = 0; l < 4; l++) {
        int flat = tid + l * 256;
        int r  = flat >> 4;
        int c4 = flat & 15;
        float4 v = make_float4(0.f,0.f,0.f,0.f);
        if (row_base + r < n)
            v = *(const float4*)(g_S1 + (size_t)row_base * D_HID + (size_t)flat * 4);
        float4 bb = __ldg((const float4*)b1 + c4);
        v.x = fmaxf(v.x + bb.x, 0.f);
        v.y = fmaxf(v.y + bb.y, 0.f);
        v.z = fmaxf(v.z + bb.z, 0.f);
        v.w = fmaxf(v.w + bb.w, 0.f);
        zs[r][c4*4+0] = v.x; zs[r][c4*4+1] = v.y;
        zs[r][c4*4+2] = v.z; zs[r][c4*4+3] = v.w;
    }
    #pragma unroll
    for (int l = 0; l < 2; l++) {
        int flat = tid + l * 256;
        ((float4*)&ws[0][0])[flat] = __ldg((const float4*)W2 + flat);
    }
    __syncthreads();

    int ty = tid >> 3;
    int tx = tid & 7;
    int col = tx * 4;

    float a00=0,a01=0,a02=0,a03=0;
    float a10=0,a11=0,a12=0,a13=0;

    #pragma unroll 16
    for (int kk = 0; kk < 64; kk++) {
        float z0 = zs[ty*2+0][kk];
        float z1 = zs[ty*2+1][kk];
        float4 b = *(float4*)&ws[kk][col];
        a00 += z0*b.x; a01 += z0*b.y; a02 += z0*b.z; a03 += z0*b.w;
        a10 += z1*b.x; a11 += z1*b.y; a12 += z1*b.z; a13 += z1*b.w;
    }

    int r0 = row_base + ty*2;
    if (r0 + 0 < n) {
        *(__half2*)(g_Z1h + (size_t)(r0+0)*D_EMB + col)     = __floats2half2_rn(a00, a01);
        *(__half2*)(g_Z1h + (size_t)(r0+0)*D_EMB + col + 2) = __floats2half2_rn(a02, a03);
    }
    if (r0 + 1 < n) {
        *(__half2*)(g_Z1h + (size_t)(r0+1)*D_EMB + col)     = __floats2half2_rn(a10, a11);
        *(__half2*)(g_Z1h + (size_t)(r0+1)*D_EMB + col + 2) = __floats2half2_rn(a12, a13);
    }
}

// ---------------------------------------------------------------------------
// SpMM d=32 (fp16 gather, smem-staged indices): 8-lane groups, 32 edges each.
// ---------------------------------------------------------------------------
__global__ __launch_bounds__(256) void spmm32_kernel(
    const int* __restrict__ src, const int* __restrict__ dst,
    const float* __restrict__ val, int nnz)
{
    __shared__ int2  sd[EPB];
    __shared__ float sv[EPB];
    stage_edges(src, dst, val, nnz, sd, sv);

    int tid = threadIdx.x;
    int c = tid & 7;
    int g = tid >> 3;                 // 32 groups
    int eb = g * 32;

    #pragma unroll 4
    for (int j = 0; j < 32; j += 4) {
        int2  e0 = sd[eb+j+0], e1 = sd[eb+j+1], e2 = sd[eb+j+2], e3 = sd[eb+j+3];
        float v0 = sv[eb+j+0], v1 = sv[eb+j+1], v2 = sv[eb+j+2], v3 = sv[eb+j+3];

        uint2 r0 = __ldg((const uint2*)(g_Z1h + (size_t)e0.x * D_EMB) + c);
        uint2 r1 = __ldg((const uint2*)(g_Z1h + (size_t)e1.x * D_EMB) + c);
        uint2 r2 = __ldg((const uint2*)(g_Z1h + (size_t)e2.x * D_EMB) + c);
        uint2 r3 = __ldg((const uint2*)(g_Z1h + (size_t)e3.x * D_EMB) + c);

        float2 f0a = __half22float2(*(__half2*)&r0.x), f0b = __half22float2(*(__half2*)&r0.y);
        float2 f1a = __half22float2(*(__half2*)&r1.x), f1b = __half22float2(*(__half2*)&r1.y);
        float2 f2a = __half22float2(*(__half2*)&r2.x), f2b = __half22float2(*(__half2*)&r2.y);
        float2 f3a = __half22float2(*(__half2*)&r3.x), f3b = __half22float2(*(__half2*)&r3.y);

        red_add_v4(g_S2 + (size_t)e0.y * D_EMB + c*4, make_float4(v0*f0a.x, v0*f0a.y, v0*f0b.x, v0*f0b.y));
        red_add_v4(g_S2 + (size_t)e1.y * D_EMB + c*4, make_float4(v1*f1a.x, v1*f1a.y, v1*f1b.x, v1*f1b.y));
        red_add_v4(g_S2 + (size_t)e2.y * D_EMB + c*4, make_float4(v2*f2a.x, v2*f2a.y, v2*f2b.x, v2*f2b.y));
        red_add_v4(g_S2 + (size_t)e3.y * D_EMB + c*4, make_float4(v3*f3a.x, v3*f3a.y, v3*f3b.x, v3*f3b.y));
    }
}

// ---------------------------------------------------------------------------
// S2 fp32 -> fp16 with fused +b2 (decoder then skips the bias).
// ---------------------------------------------------------------------------
__global__ __launch_bounds__(256) void s2half_kernel(
    const float* __restrict__ b2, int n4)
{
    int i = blockIdx.x * blockDim.x + threadIdx.x;  // over n*8 float4 groups
    if (i >= n4) return;
    float4 bb = __ldg((const float4*)b2 + (i & 7));
    float4 v = ((const float4*)g_S2)[i];
    ((__half2*)g_S2h)[i*2    ] = __floats2half2_rn(v.x + bb.x, v.y + bb.y);
    ((__half2*)g_S2h)[i*2 + 1] = __floats2half2_rn(v.z + bb.z, v.w + bb.w);
}

// ---------------------------------------------------------------------------
// Decoder (fp16 gathers, bias pre-folded): 8 lanes per edge, 2 edges/thread.
// ---------------------------------------------------------------------------
__global__ __launch_bounds__(256) void decoder_kernel(
    const int* __restrict__ edge_index, float* __restrict__ out, int ne)
{
    int t = blockIdx.x * blockDim.x + threadIdx.x;
    int c = t & 7;
    int base = (t >> 3) * 2;
    if (base >= ne) return;

    int e0 = base;
    int e1 = (base + 1 < ne) ? base + 1 : base;

    int s0 = __ldg(edge_index + e0);
    int d0 = __ldg(edge_index + ne + e0);
    int s1 = __ldg(edge_index + e1);
    int d1 = __ldg(edge_index + ne + e1);

    uint2 ra0 = __ldg((const uint2*)(g_S2h + (size_t)s0 * D_EMB) + c);
    uint2 rb0 = __ldg((const uint2*)(g_S2h + (size_t)d0 * D_EMB) + c);
    uint2 ra1 = __ldg((const uint2*)(g_S2h + (size_t)s1 * D_EMB) + c);
    uint2 rb1 = __ldg((const uint2*)(g_S2h + (size_t)d1 * D_EMB) + c);

    float2 a0l = __half22float2(*(__half2*)&ra0.x);
    float2 a0h = __half22float2(*(__half2*)&ra0.y);
    float2 b0l = __half22float2(*(__half2*)&rb0.x);
    float2 b0h = __half22float2(*(__half2*)&rb0.y);
    float2 a1l = __half22float2(*(__half2*)&ra1.x);
    float2 a1h = __half22float2(*(__half2*)&ra1.y);
    float2 b1l = __half22float2(*(__half2*)&rb1.x);
    float2 b1h = __half22float2(*(__half2*)&rb1.y);

    float p0 = a0l.x*b0l.x + a0l.y*b0l.y + a0h.x*b0h.x + a0h.y*b0h.y;
    float p1 = a1l.x*b1l.x + a1l.y*b1l.y + a1h.x*b1h.x + a1h.y*b1h.y;

    #pragma unroll
    for (int m = 1; m < 8; m <<= 1) {
        p0 += __shfl_xor_sync(0xFFFFFFFFu, p0, m);
        p1 += __shfl_xor_sync(0xFFFFFFFFu, p1, m);
    }

    if (c == 0) {
        out[e0] = p0;
        if (base + 1 < ne) out[base + 1] = p1;
    }
}

// ---------------------------------------------------------------------------
extern "C" void kernel_launch(void* const* d_in, const int* in_sizes, int n_in,
                              void* d_out, int out_size)
{
    const float* x         = (const float*)d_in[0];
    const int*   adj_src   = (const int*)  d_in[1];
    const int*   adj_dst   = (const int*)  d_in[2];
    const float* adj_val   = (const float*)d_in[3];
    const int*   edge_idx  = (const int*)  d_in[4];
    const float* W1        = (const float*)d_in[5];
    const float* b1        = (const float*)d_in[6];
    const float* W2        = (const float*)d_in[7];
    const float* b2        = (const float*)d_in[8];
    float*       out       = (float*)d_out;

    int n   = in_sizes[0] / D_IN;
    int nnz = in_sizes[3];
    int ne  = in_sizes[4] / 2;
    (void)n_in; (void)out_size;

    // GEMM1 (TF32 + cp.async, fused S1/S2 zeroing, fp16 H)
    cudaFuncSetAttribute(gemm1_tf32_v4,
                         cudaFuncAttributeMaxDynamicSharedMemorySize, GEMM1_SMEM);
    gemm1_tf32_v4<<<(n + 127) / 128, 256, GEMM1_SMEM>>>(x, W1, n);

    int eblocks = (nnz + EPB - 1) / EPB;
    // SpMM1 (d=64)
    spmm64_kernel<<<eblocks, 256>>>(adj_src, adj_dst, adj_val, nnz);
    // GEMM2 (fused relu + b1, fp16 Z1)
    gemm2_kernel<<<(n + 63) / 64, 256>>>(b1, W2, n);
    // SpMM2 (d=32)
    spmm32_kernel<<<eblocks, 256>>>(adj_src, adj_dst, adj_val, nnz);
    // S2 -> fp16 with +b2 folded
    {
        int n4 = n * 8;
        s2half_kernel<<<(n4 + 255) / 256, 256>>>(b2, n4);
    }
    // Decoder: 2 edges per 8-lane group
    {
        long long groups = ((long long)ne + 1) / 2;
        long long total  = groups * 8;
        int blocks = (int)((total + 255) / 256);
        decoder_kernel<<<blocks, 256>>>(edge_idx, out, ne);
    }
}

// round 10
// speedup vs baseline: 1.6416x; 1.6416x over previous
#include <cuda_runtime.h>
#include <cuda_fp16.h>
#include <stdint.h>

#define D_IN   256
#define D_HID  64
#define D_EMB  32
#define MAX_NODES 100000

// Scratch (static __device__ — no allocation allowed)
__device__ __half g_Hh [MAX_NODES * D_HID];  // x @ W1            (fp16)
__device__ float  g_S1 [MAX_NODES * D_HID];  // A @ H             (fp32)
__device__ __half g_Z1h[MAX_NODES * D_EMB];  // relu(S1+b1) @ W2  (fp16)
__device__ float  g_S2 [MAX_NODES * D_EMB];  // A @ Z1            (fp32)
__device__ __half g_S2h[MAX_NODES * D_EMB];  // fp16 (S2+b2) for decoder

// ---------------------------------------------------------------------------
// TF32 helpers
// ---------------------------------------------------------------------------
__device__ __forceinline__ unsigned f2tf32(float f) {
    unsigned r;
    asm("cvt.rna.tf32.f32 %0, %1;" : "=r"(r) : "f"(f));
    return r;
}
__device__ __forceinline__ unsigned bits2tf32(unsigned b) {
    unsigned r;
    asm("cvt.rna.tf32.f32 %0, %1;" : "=r"(r) : "r"(b));
    return r;
}

__device__ __forceinline__ void mma_tf32(
    float& d0, float& d1, float& d2, float& d3,
    unsigned a0, unsigned a1, unsigned a2, unsigned a3,
    unsigned b0, unsigned b1)
{
    asm volatile(
        "mma.sync.aligned.m16n8k8.row.col.f32.tf32.tf32.f32 "
        "{%0,%1,%2,%3}, {%4,%5,%6,%7}, {%8,%9}, {%0,%1,%2,%3};"
        : "+f"(d0), "+f"(d1), "+f"(d2), "+f"(d3)
        : "r"(a0), "r"(a1), "r"(a2), "r"(a3), "r"(b0), "r"(b1));
}

__device__ __forceinline__ void cp_async16(unsigned smem_addr, const void* gptr) {
    asm volatile("cp.async.cg.shared.global [%0], [%1], 16;"
                 :: "r"(smem_addr), "l"(gptr));
}

// ---------------------------------------------------------------------------
// GEMM1 (TF32 + cp.async double buffer + fused zeroing), fp16 output
// ---------------------------------------------------------------------------
#define W_STRIDE 72
#define X_STRIDE 36
#define W_WORDS  (256 * W_STRIDE)
#define X_WORDS  (128 * X_STRIDE)
#define GEMM1_SMEM ((W_WORDS + 2 * X_WORDS) * 4)

__global__ __launch_bounds__(256) void gemm1_tf32_v4(
    const float* __restrict__ x, const float* __restrict__ W1, int n)
{
    extern __shared__ unsigned smem[];
    unsigned* Wsh = smem;                       // [256][72]
    float*    xsf = (float*)(smem + W_WORDS);   // [2][128][36]

    int tid  = threadIdx.x;
    int warp = tid >> 5;
    int lane = tid & 31;
    int row_base = blockIdx.x * 128;
    int wm   = warp * 16;
    int qrow = lane >> 2;
    int qcol = lane & 3;

    unsigned xs_base;
    asm("{ .reg .u64 t; cvta.to.shared.u64 t, %1; cvt.u32.u64 %0, t; }"
        : "=r"(xs_base) : "l"(xsf));

    #pragma unroll
    for (int l = 0; l < 4; l++) {
        int flat = tid + l * 256;
        int r    = flat >> 3;
        int c4   = flat & 7;
        int grow = row_base + r; if (grow >= n) grow = n - 1;
        cp_async16(xs_base + (unsigned)(r * X_STRIDE + c4 * 4) * 4,
                   x + (size_t)grow * D_IN + c4 * 4);
    }
    asm volatile("cp.async.commit_group;");

    #pragma unroll
    for (int l = 0; l < 16; l++) {
        int flat = tid + l * 256;
        int k  = flat >> 4;
        int cc = (flat & 15) * 4;
        float4 w = __ldg((const float4*)(W1 + (size_t)k * 64 + cc));
        Wsh[k * W_STRIDE + cc + 0] = f2tf32(w.x);
        Wsh[k * W_STRIDE + cc + 1] = f2tf32(w.y);
        Wsh[k * W_STRIDE + cc + 2] = f2tf32(w.z);
        Wsh[k * W_STRIDE + cc + 3] = f2tf32(w.w);
    }

    {
        int gtid = blockIdx.x * 256 + tid;
        int nthr = gridDim.x * 256;
        float4 z = make_float4(0.f, 0.f, 0.f, 0.f);
        for (int i = gtid; i < n * 16; i += nthr) ((float4*)g_S1)[i] = z;
        for (int i = gtid; i < n * 8;  i += nthr) ((float4*)g_S2)[i] = z;
    }

    float c[8][4];
    #pragma unroll
    for (int nt = 0; nt < 8; nt++)
        #pragma unroll
        for (int i = 0; i < 4; i++) c[nt][i] = 0.f;

    #pragma unroll
    for (int kc = 0; kc < 8; kc++) {
        if (kc + 1 < 8) {
            int buf = (kc + 1) & 1;
            #pragma unroll
            for (int l = 0; l < 4; l++) {
                int flat = tid + l * 256;
                int r    = flat >> 3;
                int c4   = flat & 7;
                int grow = row_base + r; if (grow >= n) grow = n - 1;
                cp_async16(xs_base + (unsigned)(buf * X_WORDS + r * X_STRIDE + c4 * 4) * 4,
                           x + (size_t)grow * D_IN + (kc + 1) * 32 + c4 * 4);
            }
            asm volatile("cp.async.commit_group;");
            asm volatile("cp.async.wait_group 1;");
        } else {
            asm volatile("cp.async.wait_group 0;");
        }
        __syncthreads();

        const unsigned* xb = (const unsigned*)(xsf + (kc & 1) * X_WORDS);
        #pragma unroll
        for (int k8 = 0; k8 < 4; k8++) {
            int ar = wm + qrow;
            int ac = k8 * 8 + qcol;
            unsigned a0 = bits2tf32(xb[(ar    ) * X_STRIDE + ac    ]);
            unsigned a1 = bits2tf32(xb[(ar + 8) * X_STRIDE + ac    ]);
            unsigned a2 = bits2tf32(xb[(ar    ) * X_STRIDE + ac + 4]);
            unsigned a3 = bits2tf32(xb[(ar + 8) * X_STRIDE + ac + 4]);
            int kg = kc * 32 + k8 * 8 + qcol;
            #pragma unroll
            for (int nt = 0; nt < 8; nt++) {
                unsigned b0 = Wsh[(kg    ) * W_STRIDE + nt * 8 + qrow];
                unsigned b1 = Wsh[(kg + 4) * W_STRIDE + nt * 8 + qrow];
                mma_tf32(c[nt][0], c[nt][1], c[nt][2], c[nt][3],
                         a0, a1, a2, a3, b0, b1);
            }
        }
        __syncthreads();
    }

    int r0 = row_base + wm + qrow;
    int cb = qcol * 2;
    #pragma unroll
    for (int nt = 0; nt < 8; nt++) {
        if (r0 < n)
            *(__half2*)(g_Hh + (size_t)r0 * D_HID + nt*8 + cb) =
                __floats2half2_rn(c[nt][0], c[nt][1]);
        if (r0 + 8 < n)
            *(__half2*)(g_Hh + (size_t)(r0 + 8) * D_HID + nt*8 + cb) =
                __floats2half2_rn(c[nt][2], c[nt][3]);
    }
}

// ---------------------------------------------------------------------------
// red.v4 helper
// ---------------------------------------------------------------------------
__device__ __forceinline__ void red_add_v4(float* p, float4 v) {
    asm volatile("red.global.add.v4.f32 [%0], {%1,%2,%3,%4};"
                 :: "l"(p), "f"(v.x), "f"(v.y), "f"(v.z), "f"(v.w)
                 : "memory");
}

// ---------------------------------------------------------------------------
// SpMM d=64 (fp16 gather): 16 lanes per edge, 8 edges per thread (MLP=8).
// ---------------------------------------------------------------------------
__global__ __launch_bounds__(256) void spmm64_kernel(
    const int* __restrict__ src, const int* __restrict__ dst,
    const float* __restrict__ val, int nnz)
{
    int t = blockIdx.x * blockDim.x + threadIdx.x;
    int c = t & 15;
    int base = (t >> 4) * 8;
    if (base >= nnz) return;

    int   s[8], d[8];
    float v[8];
    #pragma unroll
    for (int j = 0; j < 8; j++) {
        int e = base + j;
        bool ok = (e < nnz);
        int ec = ok ? e : base;
        s[j] = __ldg(src + ec);
        d[j] = __ldg(dst + ec);
        v[j] = ok ? __ldg(val + ec) : 0.f;
    }
    uint2 raw[8];
    #pragma unroll
    for (int j = 0; j < 8; j++)
        raw[j] = __ldg((const uint2*)(g_Hh + (size_t)s[j] * D_HID) + c);
    #pragma unroll
    for (int j = 0; j < 8; j++) {
        float2 f0 = __half22float2(*(__half2*)&raw[j].x);
        float2 f1 = __half22float2(*(__half2*)&raw[j].y);
        red_add_v4(g_S1 + (size_t)d[j] * D_HID + c * 4,
                   make_float4(v[j]*f0.x, v[j]*f0.y, v[j]*f1.x, v[j]*f1.y));
    }
}

// ---------------------------------------------------------------------------
// GEMM2: Z1 = relu(S1 + b1) @ W2, fp16 output
// ---------------------------------------------------------------------------
__global__ __launch_bounds__(256) void gemm2_kernel(
    const float* __restrict__ b1, const float* __restrict__ W2, int n)
{
    __shared__ float zs[64][65];
    __shared__ float ws[64][32];

    int tid = threadIdx.x;
    int row_base = blockIdx.x * 64;

    #pragma unroll
    for (int l = 0; l < 4; l++) {
        int flat = tid + l * 256;
        int r  = flat >> 4;
        int c4 = flat & 15;
        float4 v = make_float4(0.f,0.f,0.f,0.f);
        if (row_base + r < n)
            v = *(const float4*)(g_S1 + (size_t)row_base * D_HID + (size_t)flat * 4);
        float4 bb = __ldg((const float4*)b1 + c4);
        v.x = fmaxf(v.x + bb.x, 0.f);
        v.y = fmaxf(v.y + bb.y, 0.f);
        v.z = fmaxf(v.z + bb.z, 0.f);
        v.w = fmaxf(v.w + bb.w, 0.f);
        zs[r][c4*4+0] = v.x; zs[r][c4*4+1] = v.y;
        zs[r][c4*4+2] = v.z; zs[r][c4*4+3] = v.w;
    }
    #pragma unroll
    for (int l = 0; l < 2; l++) {
        int flat = tid + l * 256;
        ((float4*)&ws[0][0])[flat] = __ldg((const float4*)W2 + flat);
    }
    __syncthreads();

    int ty = tid >> 3;
    int tx = tid & 7;
    int col = tx * 4;

    float a00=0,a01=0,a02=0,a03=0;
    float a10=0,a11=0,a12=0,a13=0;

    #pragma unroll 16
    for (int kk = 0; kk < 64; kk++) {
        float z0 = zs[ty*2+0][kk];
        float z1 = zs[ty*2+1][kk];
        float4 b = *(float4*)&ws[kk][col];
        a00 += z0*b.x; a01 += z0*b.y; a02 += z0*b.z; a03 += z0*b.w;
        a10 += z1*b.x; a11 += z1*b.y; a12 += z1*b.z; a13 += z1*b.w;
    }

    int r0 = row_base + ty*2;
    if (r0 + 0 < n) {
        *(__half2*)(g_Z1h + (size_t)(r0+0)*D_EMB + col)     = __floats2half2_rn(a00, a01);
        *(__half2*)(g_Z1h + (size_t)(r0+0)*D_EMB + col + 2) = __floats2half2_rn(a02, a03);
    }
    if (r0 + 1 < n) {
        *(__half2*)(g_Z1h + (size_t)(r0+1)*D_EMB + col)     = __floats2half2_rn(a10, a11);
        *(__half2*)(g_Z1h + (size_t)(r0+1)*D_EMB + col + 2) = __floats2half2_rn(a12, a13);
    }
}

// ---------------------------------------------------------------------------
// SpMM d=32 (fp16 gather): 8 lanes per edge, 8 edges per thread (MLP=8).
// ---------------------------------------------------------------------------
__global__ __launch_bounds__(256) void spmm32_kernel(
    const int* __restrict__ src, const int* __restrict__ dst,
    const float* __restrict__ val, int nnz)
{
    int t = blockIdx.x * blockDim.x + threadIdx.x;
    int c = t & 7;
    int base = (t >> 3) * 8;
    if (base >= nnz) return;

    int   s[8], d[8];
    float v[8];
    #pragma unroll
    for (int j = 0; j < 8; j++) {
        int e = base + j;
        bool ok = (e < nnz);
        int ec = ok ? e : base;
        s[j] = __ldg(src + ec);
        d[j] = __ldg(dst + ec);
        v[j] = ok ? __ldg(val + ec) : 0.f;
    }
    uint2 raw[8];
    #pragma unroll
    for (int j = 0; j < 8; j++)
        raw[j] = __ldg((const uint2*)(g_Z1h + (size_t)s[j] * D_EMB) + c);
    #pragma unroll
    for (int j = 0; j < 8; j++) {
        float2 f0 = __half22float2(*(__half2*)&raw[j].x);
        float2 f1 = __half22float2(*(__half2*)&raw[j].y);
        red_add_v4(g_S2 + (size_t)d[j] * D_EMB + c * 4,
                   make_float4(v[j]*f0.x, v[j]*f0.y, v[j]*f1.x, v[j]*f1.y));
    }
}

// ---------------------------------------------------------------------------
// S2 fp32 -> fp16 with fused +b2 (decoder then skips the bias).
// ---------------------------------------------------------------------------
__global__ __launch_bounds__(256) void s2half_kernel(
    const float* __restrict__ b2, int n4)
{
    int i = blockIdx.x * blockDim.x + threadIdx.x;  // over n*8 float4 groups
    if (i >= n4) return;
    float4 bb = __ldg((const float4*)b2 + (i & 7));
    float4 v = ((const float4*)g_S2)[i];
    ((__half2*)g_S2h)[i*2    ] = __floats2half2_rn(v.x + bb.x, v.y + bb.y);
    ((__half2*)g_S2h)[i*2 + 1] = __floats2half2_rn(v.z + bb.z, v.w + bb.w);
}

// ---------------------------------------------------------------------------
// Decoder (fp16 gathers, bias pre-folded): 8 lanes/edge, 4 edges per thread.
// ---------------------------------------------------------------------------
__global__ __launch_bounds__(256) void decoder_kernel(
    const int* __restrict__ edge_index, float* __restrict__ out, int ne)
{
    int t = blockIdx.x * blockDim.x + threadIdx.x;
    int c = t & 7;
    int base = (t >> 3) * 4;
    if (base >= ne) return;

    int se[4], de[4];
    #pragma unroll
    for (int j = 0; j < 4; j++) {
        int e = base + j;
        int ec = (e < ne) ? e : base;
        se[j] = __ldg(edge_index + ec);
        de[j] = __ldg(edge_index + ne + ec);
    }

    uint2 ra[4], rb[4];
    #pragma unroll
    for (int j = 0; j < 4; j++) {
        ra[j] = __ldg((const uint2*)(g_S2h + (size_t)se[j] * D_EMB) + c);
        rb[j] = __ldg((const uint2*)(g_S2h + (size_t)de[j] * D_EMB) + c);
    }

    float p[4];
    #pragma unroll
    for (int j = 0; j < 4; j++) {
        float2 al = __half22float2(*(__half2*)&ra[j].x);
        float2 ah = __half22float2(*(__half2*)&ra[j].y);
        float2 bl = __half22float2(*(__half2*)&rb[j].x);
        float2 bh = __half22float2(*(__half2*)&rb[j].y);
        p[j] = al.x*bl.x + al.y*bl.y + ah.x*bh.x + ah.y*bh.y;
    }

    #pragma unroll
    for (int m = 1; m < 8; m <<= 1) {
        #pragma unroll
        for (int j = 0; j < 4; j++)
            p[j] += __shfl_xor_sync(0xFFFFFFFFu, p[j], m);
    }

    if (c == 0) {
        if (base + 3 < ne) {
            *(float4*)(out + base) = make_float4(p[0], p[1], p[2], p[3]);
        } else {
            #pragma unroll
            for (int j = 0; j < 4; j++)
                if (base + j < ne) out[base + j] = p[j];
        }
    }
}

// ---------------------------------------------------------------------------
extern "C" void kernel_launch(void* const* d_in, const int* in_sizes, int n_in,
                              void* d_out, int out_size)
{
    const float* x         = (const float*)d_in[0];
    const int*   adj_src   = (const int*)  d_in[1];
    const int*   adj_dst   = (const int*)  d_in[2];
    const float* adj_val   = (const float*)d_in[3];
    const int*   edge_idx  = (const int*)  d_in[4];
    const float* W1        = (const float*)d_in[5];
    const float* b1        = (const float*)d_in[6];
    const float* W2        = (const float*)d_in[7];
    const float* b2        = (const float*)d_in[8];
    float*       out       = (float*)d_out;

    int n   = in_sizes[0] / D_IN;
    int nnz = in_sizes[3];
    int ne  = in_sizes[4] / 2;
    (void)n_in; (void)out_size;

    // GEMM1 (TF32 + cp.async, fused S1/S2 zeroing, fp16 H)
    cudaFuncSetAttribute(gemm1_tf32_v4,
                         cudaFuncAttributeMaxDynamicSharedMemorySize, GEMM1_SMEM);
    gemm1_tf32_v4<<<(n + 127) / 128, 256, GEMM1_SMEM>>>(x, W1, n);

    // SpMM1 (d=64): 8 edges per 16-lane group
    {
        long long groups = ((long long)nnz + 7) / 8;
        long long total  = groups * 16;
        int blocks = (int)((total + 255) / 256);
        spmm64_kernel<<<blocks, 256>>>(adj_src, adj_dst, adj_val, nnz);
    }
    // GEMM2 (fused relu + b1, fp16 Z1)
    gemm2_kernel<<<(n + 63) / 64, 256>>>(b1, W2, n);
    // SpMM2 (d=32): 8 edges per 8-lane group
    {
        long long groups = ((long long)nnz + 7) / 8;
        long long total  = groups * 8;
        int blocks = (int)((total + 255) / 256);
        spmm32_kernel<<<blocks, 256>>>(adj_src, adj_dst, adj_val, nnz);
    }
    // S2 -> fp16 with +b2 folded
    {
        int n4 = n * 8;
        s2half_kernel<<<(n4 + 255) / 256, 256>>>(b2, n4);
    }
    // Decoder: 4 edges per 8-lane group
    {
        long long groups = ((long long)ne + 3) / 4;
        long long total  = groups * 8;
        int blocks = (int)((total + 255) / 256);
        decoder_kernel<<<blocks, 256>>>(edge_idx, out, ne);
    }
}

// round 11
// speedup vs baseline: 1.6640x; 1.0137x over previous
#include <cuda_runtime.h>
#include <cuda_fp16.h>
#include <stdint.h>

#define D_IN   256
#define D_HID  64
#define D_EMB  32
#define MAX_NODES 100000

// Scratch (static __device__ — no allocation allowed)
__device__ __half g_Hh [MAX_NODES * D_HID];  // x @ W1            (fp16)
__device__ float  g_S1 [MAX_NODES * D_HID];  // A @ H             (fp32)
__device__ __half g_Z1h[MAX_NODES * D_EMB];  // relu(S1+b1) @ W2  (fp16)
__device__ float  g_S2 [MAX_NODES * D_EMB];  // A @ Z1            (fp32)
__device__ __half g_S2h[MAX_NODES * D_EMB];  // fp16 (S2+b2) for decoder

// ---------------------------------------------------------------------------
// TF32 helpers
// ---------------------------------------------------------------------------
__device__ __forceinline__ unsigned f2tf32(float f) {
    unsigned r;
    asm("cvt.rna.tf32.f32 %0, %1;" : "=r"(r) : "f"(f));
    return r;
}
__device__ __forceinline__ unsigned bits2tf32(unsigned b) {
    unsigned r;
    asm("cvt.rna.tf32.f32 %0, %1;" : "=r"(r) : "r"(b));
    return r;
}

__device__ __forceinline__ void mma_tf32(
    float& d0, float& d1, float& d2, float& d3,
    unsigned a0, unsigned a1, unsigned a2, unsigned a3,
    unsigned b0, unsigned b1)
{
    asm volatile(
        "mma.sync.aligned.m16n8k8.row.col.f32.tf32.tf32.f32 "
        "{%0,%1,%2,%3}, {%4,%5,%6,%7}, {%8,%9}, {%0,%1,%2,%3};"
        : "+f"(d0), "+f"(d1), "+f"(d2), "+f"(d3)
        : "r"(a0), "r"(a1), "r"(a2), "r"(a3), "r"(b0), "r"(b1));
}

__device__ __forceinline__ void cp_async16(unsigned smem_addr, const void* gptr) {
    asm volatile("cp.async.cg.shared.global [%0], [%1], 16;"
                 :: "r"(smem_addr), "l"(gptr));
}

// ---------------------------------------------------------------------------
// GEMM1 (TF32 + cp.async double buffer + fused zeroing), fp16 output
// ---------------------------------------------------------------------------
#define W_STRIDE 72
#define X_STRIDE 36
#define W_WORDS  (256 * W_STRIDE)
#define X_WORDS  (128 * X_STRIDE)
#define GEMM1_SMEM ((W_WORDS + 2 * X_WORDS) * 4)

__global__ __launch_bounds__(256) void gemm1_tf32_v4(
    const float* __restrict__ x, const float* __restrict__ W1, int n)
{
    extern __shared__ unsigned smem[];
    unsigned* Wsh = smem;                       // [256][72]
    float*    xsf = (float*)(smem + W_WORDS);   // [2][128][36]

    int tid  = threadIdx.x;
    int warp = tid >> 5;
    int lane = tid & 31;
    int row_base = blockIdx.x * 128;
    int wm   = warp * 16;
    int qrow = lane >> 2;
    int qcol = lane & 3;

    unsigned xs_base;
    asm("{ .reg .u64 t; cvta.to.shared.u64 t, %1; cvt.u32.u64 %0, t; }"
        : "=r"(xs_base) : "l"(xsf));

    #pragma unroll
    for (int l = 0; l < 4; l++) {
        int flat = tid + l * 256;
        int r    = flat >> 3;
        int c4   = flat & 7;
        int grow = row_base + r; if (grow >= n) grow = n - 1;
        cp_async16(xs_base + (unsigned)(r * X_STRIDE + c4 * 4) * 4,
                   x + (size_t)grow * D_IN + c4 * 4);
    }
    asm volatile("cp.async.commit_group;");

    #pragma unroll
    for (int l = 0; l < 16; l++) {
        int flat = tid + l * 256;
        int k  = flat >> 4;
        int cc = (flat & 15) * 4;
        float4 w = __ldg((const float4*)(W1 + (size_t)k * 64 + cc));
        Wsh[k * W_STRIDE + cc + 0] = f2tf32(w.x);
        Wsh[k * W_STRIDE + cc + 1] = f2tf32(w.y);
        Wsh[k * W_STRIDE + cc + 2] = f2tf32(w.z);
        Wsh[k * W_STRIDE + cc + 3] = f2tf32(w.w);
    }

    {
        int gtid = blockIdx.x * 256 + tid;
        int nthr = gridDim.x * 256;
        float4 z = make_float4(0.f, 0.f, 0.f, 0.f);
        for (int i = gtid; i < n * 16; i += nthr) ((float4*)g_S1)[i] = z;
        for (int i = gtid; i < n * 8;  i += nthr) ((float4*)g_S2)[i] = z;
    }

    float c[8][4];
    #pragma unroll
    for (int nt = 0; nt < 8; nt++)
        #pragma unroll
        for (int i = 0; i < 4; i++) c[nt][i] = 0.f;

    #pragma unroll
    for (int kc = 0; kc < 8; kc++) {
        if (kc + 1 < 8) {
            int buf = (kc + 1) & 1;
            #pragma unroll
            for (int l = 0; l < 4; l++) {
                int flat = tid + l * 256;
                int r    = flat >> 3;
                int c4   = flat & 7;
                int grow = row_base + r; if (grow >= n) grow = n - 1;
                cp_async16(xs_base + (unsigned)(buf * X_WORDS + r * X_STRIDE + c4 * 4) * 4,
                           x + (size_t)grow * D_IN + (kc + 1) * 32 + c4 * 4);
            }
            asm volatile("cp.async.commit_group;");
            asm volatile("cp.async.wait_group 1;");
        } else {
            asm volatile("cp.async.wait_group 0;");
        }
        __syncthreads();

        const unsigned* xb = (const unsigned*)(xsf + (kc & 1) * X_WORDS);
        #pragma unroll
        for (int k8 = 0; k8 < 4; k8++) {
            int ar = wm + qrow;
            int ac = k8 * 8 + qcol;
            unsigned a0 = bits2tf32(xb[(ar    ) * X_STRIDE + ac    ]);
            unsigned a1 = bits2tf32(xb[(ar + 8) * X_STRIDE + ac    ]);
            unsigned a2 = bits2tf32(xb[(ar    ) * X_STRIDE + ac + 4]);
            unsigned a3 = bits2tf32(xb[(ar + 8) * X_STRIDE + ac + 4]);
            int kg = kc * 32 + k8 * 8 + qcol;
            #pragma unroll
            for (int nt = 0; nt < 8; nt++) {
                unsigned b0 = Wsh[(kg    ) * W_STRIDE + nt * 8 + qrow];
                unsigned b1 = Wsh[(kg + 4) * W_STRIDE + nt * 8 + qrow];
                mma_tf32(c[nt][0], c[nt][1], c[nt][2], c[nt][3],
                         a0, a1, a2, a3, b0, b1);
            }
        }
        __syncthreads();
    }

    int r0 = row_base + wm + qrow;
    int cb = qcol * 2;
    #pragma unroll
    for (int nt = 0; nt < 8; nt++) {
        if (r0 < n)
            *(__half2*)(g_Hh + (size_t)r0 * D_HID + nt*8 + cb) =
                __floats2half2_rn(c[nt][0], c[nt][1]);
        if (r0 + 8 < n)
            *(__half2*)(g_Hh + (size_t)(r0 + 8) * D_HID + nt*8 + cb) =
                __floats2half2_rn(c[nt][2], c[nt][3]);
    }
}

// ---------------------------------------------------------------------------
// red.v4 helper
// ---------------------------------------------------------------------------
__device__ __forceinline__ void red_add_v4(float* p, float4 v) {
    asm volatile("red.global.add.v4.f32 [%0], {%1,%2,%3,%4};"
                 :: "l"(p), "f"(v.x), "f"(v.y), "f"(v.z), "f"(v.w)
                 : "memory");
}

// ---------------------------------------------------------------------------
// SpMM d=64: warp owns 32 edges; coalesced index loads + shfl distribution.
// 16-lane groups (2 per warp), 16 j-iterations.
// ---------------------------------------------------------------------------
__global__ __launch_bounds__(256) void spmm64_kernel(
    const int* __restrict__ src, const int* __restrict__ dst,
    const float* __restrict__ val, int nnz)
{
    int lane = threadIdx.x & 31;
    long long wid = (long long)((blockIdx.x * blockDim.x + threadIdx.x) >> 5);
    long long wbase = wid * 32;
    if (wbase >= nnz) return;

    long long e = wbase + lane;
    bool ok = (e < nnz);
    long long ec = ok ? e : (nnz - 1);
    int   s = __ldg(src + ec);
    int   d = __ldg(dst + ec);
    float v = ok ? __ldg(val + ec) : 0.f;

    int g = lane >> 4;          // group 0/1
    int c = lane & 15;          // channel quad

    #pragma unroll
    for (int j = 0; j < 16; j++) {
        int sl = g * 16 + j;
        int   sj = __shfl_sync(0xFFFFFFFFu, s, sl);
        int   dj = __shfl_sync(0xFFFFFFFFu, d, sl);
        float vj = __shfl_sync(0xFFFFFFFFu, v, sl);
        uint2 raw = __ldg((const uint2*)(g_Hh + (size_t)sj * D_HID) + c);
        float2 f0 = __half22float2(*(__half2*)&raw.x);
        float2 f1 = __half22float2(*(__half2*)&raw.y);
        red_add_v4(g_S1 + (size_t)dj * D_HID + c * 4,
                   make_float4(vj*f0.x, vj*f0.y, vj*f1.x, vj*f1.y));
    }
}

// ---------------------------------------------------------------------------
// GEMM2: Z1 = relu(S1 + b1) @ W2, fp16 output
// ---------------------------------------------------------------------------
__global__ __launch_bounds__(256) void gemm2_kernel(
    const float* __restrict__ b1, const float* __restrict__ W2, int n)
{
    __shared__ float zs[64][65];
    __shared__ float ws[64][32];

    int tid = threadIdx.x;
    int row_base = blockIdx.x * 64;

    #pragma unroll
    for (int l = 0; l < 4; l++) {
        int flat = tid + l * 256;
        int r  = flat >> 4;
        int c4 = flat & 15;
        float4 v = make_float4(0.f,0.f,0.f,0.f);
        if (row_base + r < n)
            v = *(const float4*)(g_S1 + (size_t)row_base * D_HID + (size_t)flat * 4);
        float4 bb = __ldg((const float4*)b1 + c4);
        v.x = fmaxf(v.x + bb.x, 0.f);
        v.y = fmaxf(v.y + bb.y, 0.f);
        v.z = fmaxf(v.z + bb.z, 0.f);
        v.w = fmaxf(v.w + bb.w, 0.f);
        zs[r][c4*4+0] = v.x; zs[r][c4*4+1] = v.y;
        zs[r][c4*4+2] = v.z; zs[r][c4*4+3] = v.w;
    }
    #pragma unroll
    for (int l = 0; l < 2; l++) {
        int flat = tid + l * 256;
        ((float4*)&ws[0][0])[flat] = __ldg((const float4*)W2 + flat);
    }
    __syncthreads();

    int ty = tid >> 3;
    int tx = tid & 7;
    int col = tx * 4;

    float a00=0,a01=0,a02=0,a03=0;
    float a10=0,a11=0,a12=0,a13=0;

    #pragma unroll 16
    for (int kk = 0; kk < 64; kk++) {
        float z0 = zs[ty*2+0][kk];
        float z1 = zs[ty*2+1][kk];
        float4 b = *(float4*)&ws[kk][col];
        a00 += z0*b.x; a01 += z0*b.y; a02 += z0*b.z; a03 += z0*b.w;
        a10 += z1*b.x; a11 += z1*b.y; a12 += z1*b.z; a13 += z1*b.w;
    }

    int r0 = row_base + ty*2;
    if (r0 + 0 < n) {
        *(__half2*)(g_Z1h + (size_t)(r0+0)*D_EMB + col)     = __floats2half2_rn(a00, a01);
        *(__half2*)(g_Z1h + (size_t)(r0+0)*D_EMB + col + 2) = __floats2half2_rn(a02, a03);
    }
    if (r0 + 1 < n) {
        *(__half2*)(g_Z1h + (size_t)(r0+1)*D_EMB + col)     = __floats2half2_rn(a10, a11);
        *(__half2*)(g_Z1h + (size_t)(r0+1)*D_EMB + col + 2) = __floats2half2_rn(a12, a13);
    }
}

// ---------------------------------------------------------------------------
// SpMM d=32: warp owns 32 edges; coalesced index loads + shfl distribution.
// 8-lane groups (4 per warp), 8 j-iterations.
// ---------------------------------------------------------------------------
__global__ __launch_bounds__(256) void spmm32_kernel(
    const int* __restrict__ src, const int* __restrict__ dst,
    const float* __restrict__ val, int nnz)
{
    int lane = threadIdx.x & 31;
    long long wid = (long long)((blockIdx.x * blockDim.x + threadIdx.x) >> 5);
    long long wbase = wid * 32;
    if (wbase >= nnz) return;

    long long e = wbase + lane;
    bool ok = (e < nnz);
    long long ec = ok ? e : (nnz - 1);
    int   s = __ldg(src + ec);
    int   d = __ldg(dst + ec);
    float v = ok ? __ldg(val + ec) : 0.f;

    int g = lane >> 3;          // group 0..3
    int c = lane & 7;

    #pragma unroll
    for (int j = 0; j < 8; j++) {
        int sl = g * 8 + j;
        int   sj = __shfl_sync(0xFFFFFFFFu, s, sl);
        int   dj = __shfl_sync(0xFFFFFFFFu, d, sl);
        float vj = __shfl_sync(0xFFFFFFFFu, v, sl);
        uint2 raw = __ldg((const uint2*)(g_Z1h + (size_t)sj * D_EMB) + c);
        float2 f0 = __half22float2(*(__half2*)&raw.x);
        float2 f1 = __half22float2(*(__half2*)&raw.y);
        red_add_v4(g_S2 + (size_t)dj * D_EMB + c * 4,
                   make_float4(vj*f0.x, vj*f0.y, vj*f1.x, vj*f1.y));
    }
}

// ---------------------------------------------------------------------------
// S2 fp32 -> fp16 with fused +b2 (decoder then skips the bias).
// ---------------------------------------------------------------------------
__global__ __launch_bounds__(256) void s2half_kernel(
    const float* __restrict__ b2, int n4)
{
    int i = blockIdx.x * blockDim.x + threadIdx.x;  // over n*8 float4 groups
    if (i >= n4) return;
    float4 bb = __ldg((const float4*)b2 + (i & 7));
    float4 v = ((const float4*)g_S2)[i];
    ((__half2*)g_S2h)[i*2    ] = __floats2half2_rn(v.x + bb.x, v.y + bb.y);
    ((__half2*)g_S2h)[i*2 + 1] = __floats2half2_rn(v.z + bb.z, v.w + bb.w);
}

// ---------------------------------------------------------------------------
// Decoder: warp owns 32 edges; coalesced index loads + shfl distribution.
// 8-lane groups, 8 j-iterations, bias pre-folded into g_S2h.
// ---------------------------------------------------------------------------
__global__ __launch_bounds__(256) void decoder_kernel(
    const int* __restrict__ edge_index, float* __restrict__ out, int ne)
{
    int lane = threadIdx.x & 31;
    long long wid = (long long)((blockIdx.x * blockDim.x + threadIdx.x) >> 5);
    long long wbase = wid * 32;
    if (wbase >= ne) return;

    long long e = wbase + lane;
    bool ok = (e < ne);
    long long ec = ok ? e : (ne - 1);
    int s = __ldg(edge_index + ec);
    int d = __ldg(edge_index + ne + ec);

    int g = lane >> 3;
    int c = lane & 7;

    float p[8];
    #pragma unroll
    for (int j = 0; j < 8; j++) {
        int sl = g * 8 + j;
        int sj = __shfl_sync(0xFFFFFFFFu, s, sl);
        int dj = __shfl_sync(0xFFFFFFFFu, d, sl);
        uint2 ra = __ldg((const uint2*)(g_S2h + (size_t)sj * D_EMB) + c);
        uint2 rb = __ldg((const uint2*)(g_S2h + (size_t)dj * D_EMB) + c);
        float2 al = __half22float2(*(__half2*)&ra.x);
        float2 ah = __half22float2(*(__half2*)&ra.y);
        float2 bl = __half22float2(*(__half2*)&rb.x);
        float2 bh = __half22float2(*(__half2*)&rb.y);
        p[j] = al.x*bl.x + al.y*bl.y + ah.x*bh.x + ah.y*bh.y;
    }

    // reduce each p[j] over the 8 lanes of the group
    #pragma unroll
    for (int m = 1; m < 8; m <<= 1) {
        #pragma unroll
        for (int j = 0; j < 8; j++)
            p[j] += __shfl_xor_sync(0xFFFFFFFFu, p[j], m);
    }

    // lane c==j of each group writes edge (wbase + g*8 + j): coalesced-ish
    long long eo = wbase + g * 8 + c;
    if (eo < ne) out[eo] = p[c];
}

// ---------------------------------------------------------------------------
extern "C" void kernel_launch(void* const* d_in, const int* in_sizes, int n_in,
                              void* d_out, int out_size)
{
    const float* x         = (const float*)d_in[0];
    const int*   adj_src   = (const int*)  d_in[1];
    const int*   adj_dst   = (const int*)  d_in[2];
    const float* adj_val   = (const float*)d_in[3];
    const int*   edge_idx  = (const int*)  d_in[4];
    const float* W1        = (const float*)d_in[5];
    const float* b1        = (const float*)d_in[6];
    const float* W2        = (const float*)d_in[7];
    const float* b2        = (const float*)d_in[8];
    float*       out       = (float*)d_out;

    int n   = in_sizes[0] / D_IN;
    int nnz = in_sizes[3];
    int ne  = in_sizes[4] / 2;
    (void)n_in; (void)out_size;

    // GEMM1 (TF32 + cp.async, fused S1/S2 zeroing, fp16 H)
    cudaFuncSetAttribute(gemm1_tf32_v4,
                         cudaFuncAttributeMaxDynamicSharedMemorySize, GEMM1_SMEM);
    gemm1_tf32_v4<<<(n + 127) / 128, 256, GEMM1_SMEM>>>(x, W1, n);

    // SpMM1 (d=64): 1 warp per 32 edges
    {
        long long warps = ((long long)nnz + 31) / 32;
        long long total = warps * 32;
        int blocks = (int)((total + 255) / 256);
        spmm64_kernel<<<blocks, 256>>>(adj_src, adj_dst, adj_val, nnz);
    }
    // GEMM2 (fused relu + b1, fp16 Z1)
    gemm2_kernel<<<(n + 63) / 64, 256>>>(b1, W2, n);
    // SpMM2 (d=32): 1 warp per 32 edges
    {
        long long warps = ((long long)nnz + 31) / 32;
        long long total = warps * 32;
        int blocks = (int)((total + 255) / 256);
        spmm32_kernel<<<blocks, 256>>>(adj_src, adj_dst, adj_val, nnz);
    }
    // S2 -> fp16 with +b2 folded
    {
        int n4 = n * 8;
        s2half_kernel<<<(n4 + 255) / 256, 256>>>(b2, n4);
    }
    // Decoder: 1 warp per 32 edges
    {
        long long warps = ((long long)ne + 31) / 32;
        long long total = warps * 32;
        int blocks = (int)((total + 255) / 256);
        decoder_kernel<<<blocks, 256>>>(edge_idx, out, ne);
    }
}